// round 1
// baseline (speedup 1.0000x reference)
#include <cuda_runtime.h>

#define NC 128
#define NS 128
#define EPS 1e-5f

__device__ __forceinline__ float warp_incl_scan(float v, int lane) {
    #pragma unroll
    for (int o = 1; o < 32; o <<= 1) {
        float n = __shfl_up_sync(0xffffffffu, v, o);
        if (lane >= o) v += n;
    }
    return v;
}

__global__ __launch_bounds__(128) void pdf_sampler_kernel(
    const float* __restrict__ deltas,
    const float* __restrict__ density,
    const float* __restrict__ bins,
    const float* __restrict__ u,
    float* __restrict__ out)
{
    const int ray  = blockIdx.x;
    const int t    = threadIdx.x;
    const int lane = t & 31;
    const int wid  = t >> 5;

    __shared__ float cdf_sh[NC + 1];
    __shared__ float bins_sh[NC + 1];
    __shared__ float wtot[4];

    const size_t base_c = (size_t)ray * NC;
    const size_t base_b = (size_t)ray * (NC + 1);

    // Coalesced loads
    float d   = deltas[base_c + t];
    float rho = density[base_c + t];
    bins_sh[t] = bins[base_b + t];
    if (t == 0) bins_sh[NC] = bins[base_b + NC];
    float uu = u[base_c + t];

    // delta * density
    float dd = d * rho;

    // --- scan 1: inclusive cumsum of dd (for transmittance) ---
    float s = warp_incl_scan(dd, lane);
    if (lane == 31) wtot[wid] = s;
    __syncthreads();
    float off = 0.0f;
    #pragma unroll
    for (int i = 0; i < 4; i++)
        if (i < wid) off += wtot[i];
    float excl = (s + off) - dd;                 // exclusive cumsum
    float trans = __expf(-excl);
    float alpha = 1.0f - __expf(-dd);
    float w = alpha * trans;
    __syncthreads();                             // wtot reuse

    // --- scan 2: inclusive cumsum of w (for CDF) + total ---
    float sw = warp_incl_scan(w, lane);
    if (lane == 31) wtot[wid] = sw;
    __syncthreads();
    float off2 = 0.0f;
    #pragma unroll
    for (int i = 0; i < 4; i++)
        if (i < wid) off2 += wtot[i];
    float cw   = sw + off2;
    float wsum = wtot[0] + wtot[1] + wtot[2] + wtot[3];

    float pad  = fmaxf(EPS - wsum, 0.0f);
    float inv_total = 1.0f / (wsum + pad);
    // cumsum(pdf)[t] = (cumsum(w)[t] + pad*(t+1)/NC) / (wsum + pad)
    float c = fminf(1.0f, (cw + pad * (float)(t + 1) * (1.0f / (float)NC)) * inv_total);
    cdf_sh[t + 1] = c;
    if (t == 0) cdf_sh[0] = 0.0f;
    __syncthreads();

    // --- searchsorted(cdf, u, side='right') over 129 entries ---
    int lo = 0, hi = NC + 1;
    #pragma unroll
    for (int it = 0; it < 8; it++) {             // ceil(log2(129)) = 8
        if (lo < hi) {
            int mid = (lo + hi) >> 1;
            if (cdf_sh[mid] <= uu) lo = mid + 1; else hi = mid;
        }
    }
    int below = max(lo - 1, 0);
    int above = min(lo, NC);

    float c0 = cdf_sh[below];
    float c1 = cdf_sh[above];
    float b0 = bins_sh[below];
    float b1 = bins_sh[above];

    float den = c1 - c0;
    den = (den < EPS) ? 1.0f : den;
    float frac = (uu - c0) / den;
    out[base_c + t] = b0 + frac * (b1 - b0);
}

extern "C" void kernel_launch(void* const* d_in, const int* in_sizes, int n_in,
                              void* d_out, int out_size) {
    const float* deltas  = (const float*)d_in[0];
    const float* density = (const float*)d_in[1];
    const float* bins    = (const float*)d_in[2];
    const float* u       = (const float*)d_in[3];
    float* out = (float*)d_out;

    int R = in_sizes[0] / NC;   // 131072
    pdf_sampler_kernel<<<R, 128>>>(deltas, density, bins, u, out);
}

// round 2
// speedup vs baseline: 2.1533x; 2.1533x over previous
#include <cuda_runtime.h>

#define NC 128
#define EPS 1e-5f
#define RAYS_PER_CTA 8          // 8 warps/CTA, one ray per warp
#define THREADS (RAYS_PER_CTA * 32)

__device__ __forceinline__ float warp_incl_scan(float v, int lane) {
    #pragma unroll
    for (int o = 1; o < 32; o <<= 1) {
        float n = __shfl_up_sync(0xffffffffu, v, o);
        if (lane >= o) v += n;
    }
    return v;
}

__global__ __launch_bounds__(THREADS) void pdf_sampler_kernel(
    const float* __restrict__ deltas,
    const float* __restrict__ density,
    const float* __restrict__ bins,
    const float* __restrict__ u,
    float* __restrict__ out)
{
    const int lane = threadIdx.x & 31;
    const int wrp  = threadIdx.x >> 5;
    const int ray  = blockIdx.x * RAYS_PER_CTA + wrp;

    __shared__ float cdfv_sh[RAYS_PER_CTA][NC];      // holds cdf[1..128]
    __shared__ float bins_sh[RAYS_PER_CTA][NC + 1];

    const size_t base_c = (size_t)ray * NC;
    const size_t base_b = (size_t)ray * (NC + 1);

    // ---- coalesced loads ----
    const float4 dv = *(const float4*)(deltas  + base_c + 4 * lane);
    const float4 rv = *(const float4*)(density + base_c + 4 * lane);
    const float4 uv = *(const float4*)(u       + base_c + 4 * lane);

    // bins: stride-129 rows -> misaligned for float4; interleaved scalar loads
    bins_sh[wrp][lane]      = bins[base_b + lane];
    bins_sh[wrp][lane + 32] = bins[base_b + lane + 32];
    bins_sh[wrp][lane + 64] = bins[base_b + lane + 64];
    bins_sh[wrp][lane + 96] = bins[base_b + lane + 96];
    if (lane == 0) bins_sh[wrp][NC] = bins[base_b + NC];

    // ---- dd = delta * density, per-lane serial prefix ----
    const float dd0 = dv.x * rv.x;
    const float dd1 = dv.y * rv.y;
    const float dd2 = dv.z * rv.z;
    const float dd3 = dv.w * rv.w;
    const float p0 = dd0;
    const float p1 = p0 + dd1;
    const float p2 = p1 + dd2;
    const float p3 = p2 + dd3;

    // warp scan of lane totals -> exclusive offset
    float incl = warp_incl_scan(p3, lane);
    float off  = incl - p3;

    // exclusive cumsum per element; weights
    const float w0 = (1.0f - __expf(-dd0)) * __expf(-(off));
    const float w1 = (1.0f - __expf(-dd1)) * __expf(-(off + p0));
    const float w2 = (1.0f - __expf(-dd2)) * __expf(-(off + p1));
    const float w3 = (1.0f - __expf(-dd3)) * __expf(-(off + p2));

    // ---- cumsum of weights ----
    const float q0 = w0;
    const float q1 = q0 + w1;
    const float q2 = q1 + w2;
    const float q3 = q2 + w3;
    float incl2 = warp_incl_scan(q3, lane);
    float off2  = incl2 - q3;

    const float wsum = __shfl_sync(0xffffffffu, incl2, 31);
    const float pad  = fmaxf(EPS - wsum, 0.0f);
    const float inv  = 1.0f / (wsum + pad);
    const float ps   = pad * (1.0f / (float)NC);

    const int e = 4 * lane;   // element index of .x
    float4 cv;
    cv.x = fminf(1.0f, (off2 + q0 + ps * (float)(e + 1)) * inv);
    cv.y = fminf(1.0f, (off2 + q1 + ps * (float)(e + 2)) * inv);
    cv.z = fminf(1.0f, (off2 + q2 + ps * (float)(e + 3)) * inv);
    cv.w = fminf(1.0f, (off2 + q3 + ps * (float)(e + 4)) * inv);
    *(float4*)(&cdfv_sh[wrp][4 * lane]) = cv;   // aligned, conflict-free

    __syncwarp();

    // ---- per-sample inverse CDF ----
    // searchsorted(cdf, u, 'right') over cdf[0..128] with cdf[0]=0 <= u always:
    // idx = 1 + (#entries of cdfv (=cdf[1..128]) <= u). Branch-free upper bound.
    const float* __restrict__ cd = cdfv_sh[wrp];
    const float* __restrict__ bn = bins_sh[wrp];
    float4 res;

    #pragma unroll
    for (int i = 0; i < 4; i++) {
        const float uu = (i == 0) ? uv.x : (i == 1) ? uv.y : (i == 2) ? uv.z : uv.w;
        int pos = 0;
        #pragma unroll
        for (int step = 64; step >= 1; step >>= 1) {
            int np = pos + step;
            if (cd[np - 1] <= uu) pos = np;
        }
        // idx = pos+1; below = pos; above = min(pos+1, 128)
        const float c0 = (pos == 0) ? 0.0f : cd[pos - 1];
        const float c1 = cd[(pos < 127) ? pos : 127];
        const float b0 = bn[pos];
        const float b1 = bn[(pos + 1 < NC) ? (pos + 1) : NC];

        float den = c1 - c0;
        den = (den < EPS) ? 1.0f : den;
        const float frac = (uu - c0) / den;
        const float s = b0 + frac * (b1 - b0);
        if (i == 0) res.x = s; else if (i == 1) res.y = s; else if (i == 2) res.z = s; else res.w = s;
    }

    *(float4*)(out + base_c + 4 * lane) = res;
}

extern "C" void kernel_launch(void* const* d_in, const int* in_sizes, int n_in,
                              void* d_out, int out_size) {
    const float* deltas  = (const float*)d_in[0];
    const float* density = (const float*)d_in[1];
    const float* bins    = (const float*)d_in[2];
    const float* u       = (const float*)d_in[3];
    float* out = (float*)d_out;

    int R = in_sizes[0] / NC;               // 131072
    pdf_sampler_kernel<<<R / RAYS_PER_CTA, THREADS>>>(deltas, density, bins, u, out);
}